// round 8
// baseline (speedup 1.0000x reference)
#include <cuda_runtime.h>
#include <mma.h>
#include <math.h>

using namespace nvcuda;

#define Nn 50000
#define Ee 800000
#define Dd 128
#define Gg 500
#define NSs 100
#define M0 64
#define SLOPE 0.2f
#define BN_EPS 1e-5f

#define SCAN_BLK 512
#define SCAN_NB ((Nn + SCAN_BLK - 1) / SCAN_BLK)   // 98

// -------- scratch (device globals; no allocation allowed) --------
// NEVER pass these names from host code directly (host shadow + ATS trap);
// always cudaGetSymbolAddress.
__device__ float g_xl[Nn * Dd];
__device__ float g_xr[Nn * Dd];
__device__ float g_h1[Nn * Dd];
__device__ float g_h2[Nn * Dd];
__device__ float g_pooled[Gg * Dd];
__device__ int   g_src[Ee];
__device__ int   g_dst[Ee];
__device__ int   g_counts[Nn];
__device__ int   g_incl[Nn];
__device__ int   g_rowPtr[Nn + 1];
__device__ int   g_head[Nn];
__device__ int   g_csr_src[Ee];
__device__ int   g_blockSums[SCAN_NB + 8];
__device__ int   g_blockOff[SCAN_NB + 8];
__device__ int   g_gcounts[Gg];
__device__ int   g_gstart[Gg + 1];

// ---------------- decode + zero (merged; grid covers Ee >= Nn) ----------------
__global__ void k_decode_zero(const int* __restrict__ gd) {
    int i = blockIdx.x * blockDim.x + threadIdx.x;
    if (i < Nn) g_counts[i] = 0;
    if (i < Gg) g_gcounts[i] = 0;
    if (i >= Ee) return;
    bool w64 = (gd[1] == 0 && gd[3] == 0 && gd[5] == 0 && gd[7] == 0);
    if (w64) {
        g_src[i] = gd[2 * i];
        g_dst[i] = gd[2 * Ee + 2 * i];
    } else {
        g_src[i] = gd[i];
        g_dst[i] = gd[Ee + i];
    }
}

// ---------------- both histograms (merged) ----------------
__global__ void k_hist(const int* __restrict__ batch) {
    int i = blockIdx.x * blockDim.x + threadIdx.x;
    if (i < Ee) atomicAdd(&g_counts[g_dst[i]], 1);
    if (i < Nn) atomicAdd(&g_gcounts[batch[i]], 1);
}

// ---------------- scan (counts -> rowPtr) ----------------
__global__ void k_scan1() {
    __shared__ int s[SCAN_BLK];
    int tid = threadIdx.x;
    int i = blockIdx.x * SCAN_BLK + tid;
    int v = (i < Nn) ? g_counts[i] : 0;
    s[tid] = v;
    __syncthreads();
    for (int off = 1; off < SCAN_BLK; off <<= 1) {
        int add = (tid >= off) ? s[tid - off] : 0;
        __syncthreads();
        s[tid] += add;
        __syncthreads();
    }
    if (i < Nn) g_incl[i] = s[tid];
    if (tid == SCAN_BLK - 1) g_blockSums[blockIdx.x] = s[tid];
}
// block 0: block-offset scan; block 1: graph-range scan
__global__ void k_scan2_gscan() {
    if (threadIdx.x != 0) return;
    if (blockIdx.x == 0) {
        int run = 0;
        for (int b = 0; b < SCAN_NB; b++) { g_blockOff[b] = run; run += g_blockSums[b]; }
    } else {
        int run = 0;
        for (int g = 0; g < Gg; g++) { g_gstart[g] = run; run += g_gcounts[g]; }
        g_gstart[Gg] = run;
    }
}
__global__ void k_scan3() {
    int i = blockIdx.x * blockDim.x + threadIdx.x;
    if (i < Nn) {
        int tot = g_incl[i] + g_blockOff[i / SCAN_BLK];
        int excl = tot - g_counts[i];
        g_rowPtr[i] = excl;
        g_head[i] = excl;
        if (i == Nn - 1) g_rowPtr[Nn] = tot;
    }
}
__global__ void k_fill() {
    int i = blockIdx.x * blockDim.x + threadIdx.x;
    if (i < Ee) {
        int pos = atomicAdd(&g_head[g_dst[i]], 1);
        g_csr_src[pos] = g_src[i];
    }
}

// ---------------- tensor-core node GEMM (3xTF32): C[nrows,128] = A @ W + bias --------
// block: 64 rows x 128 cols, 8 warps (4 m-rows x 2 n-halves), each warp 16x64.
__global__ void k_gemm_tc(const float* __restrict__ A, const float* __restrict__ W,
                          const float* __restrict__ bias, float* __restrict__ C,
                          int nrows) {
    __shared__ float sm[8192];          // 32 KB: As [64][32] + Bs [32][128]; reused for epilogue
    float* As = sm;                     // 2048 floats
    float* Bs = sm + 2048;              // 4096 floats
    int tid = threadIdx.x;
    int wid = tid >> 5;
    int warp_m = wid >> 1;              // 0..3
    int warp_n = wid & 1;               // 0..1
    int rowBase = blockIdx.x * 64;

    wmma::fragment<wmma::accumulator, 16, 16, 8, float> acc[4];
#pragma unroll
    for (int i = 0; i < 4; i++) wmma::fill_fragment(acc[i], 0.f);

    for (int k0 = 0; k0 < 128; k0 += 32) {
        __syncthreads();
        // stage A 64x32 (guarded rows), 2 float4 per thread
#pragma unroll
        for (int i = 0; i < 2; i++) {
            int idx = tid + i * 256;        // 0..511
            int r = idx >> 3, c4 = idx & 7;
            int gr = rowBase + r;
            float4 v = make_float4(0.f, 0.f, 0.f, 0.f);
            if (gr < nrows) v = *(const float4*)(A + gr * 128 + k0 + c4 * 4);
            *(float4*)(As + r * 32 + c4 * 4) = v;
        }
        // stage B 32x128, 4 float4 per thread
#pragma unroll
        for (int i = 0; i < 4; i++) {
            int idx = tid + i * 256;        // 0..1023
            int r = idx >> 5, c4 = idx & 31;
            *(float4*)(Bs + r * 128 + c4 * 4) =
                *(const float4*)(W + (k0 + r) * 128 + c4 * 4);
        }
        __syncthreads();
#pragma unroll
        for (int kk = 0; kk < 32; kk += 8) {
            wmma::fragment<wmma::matrix_a, 16, 16, 8, wmma::precision::tf32, wmma::row_major> af, ah, al;
            wmma::load_matrix_sync(af, As + warp_m * 16 * 32 + kk, 32);
#pragma unroll
            for (int e = 0; e < af.num_elements; e++) {
                float v = af.x[e];
                float hi = wmma::__float_to_tf32(v);
                ah.x[e] = hi;
                al.x[e] = wmma::__float_to_tf32(v - hi);
            }
#pragma unroll
            for (int nt = 0; nt < 4; nt++) {
                wmma::fragment<wmma::matrix_b, 16, 16, 8, wmma::precision::tf32, wmma::row_major> bf, bh, bl;
                wmma::load_matrix_sync(bf, Bs + kk * 128 + warp_n * 64 + nt * 16, 128);
#pragma unroll
                for (int e = 0; e < bf.num_elements; e++) {
                    float v = bf.x[e];
                    float hi = wmma::__float_to_tf32(v);
                    bh.x[e] = hi;
                    bl.x[e] = wmma::__float_to_tf32(v - hi);
                }
                // 3xTF32: small terms first, then hi*hi
                wmma::mma_sync(acc[nt], al, bh, acc[nt]);
                wmma::mma_sync(acc[nt], ah, bl, acc[nt]);
                wmma::mma_sync(acc[nt], ah, bh, acc[nt]);
            }
        }
    }
    __syncthreads();
#pragma unroll
    for (int nt = 0; nt < 4; nt++)
        wmma::store_matrix_sync(sm + warp_m * 16 * 128 + warp_n * 64 + nt * 16,
                                acc[nt], 128, wmma::mem_row_major);
    __syncthreads();
    // epilogue: add bias, write out (coalesced float4)
#pragma unroll
    for (int i = 0; i < 8; i++) {
        int idx = tid + i * 256;            // 0..2047 (float4 units)
        int r = idx >> 5, c4 = idx & 31;
        int gr = rowBase + r;
        if (gr < nrows) {
            float4 v = *(float4*)(sm + r * 128 + c4 * 4);
            float4 bv = *(const float4*)(bias + c4 * 4);
            v.x += bv.x; v.y += bv.y; v.z += bv.z; v.w += bv.w;
            *(float4*)(C + gr * 128 + c4 * 4) = v;
        }
    }
}

// ---------------- GATv2 aggregate: warp per node, ONLINE softmax (1 sweep) ----------
__global__ void k_aggregate(const float* __restrict__ xl, const float* __restrict__ xr,
                            const float* __restrict__ att, const float* __restrict__ bias,
                            float* __restrict__ out,
                            int do_bn,
                            const float* __restrict__ gamma, const float* __restrict__ beta,
                            const float* __restrict__ mean, const float* __restrict__ var) {
    int warpId = (blockIdx.x * blockDim.x + threadIdx.x) >> 5;
    if (warpId >= Nn) return;
    int lane = threadIdx.x & 31;
    int d = warpId;
    int s0 = g_rowPtr[d], s1 = g_rowPtr[d + 1];

    float xrv[4], attv[4];
#pragma unroll
    for (int i = 0; i < 4; i++) {
        xrv[i] = xr[d * 128 + lane + 32 * i];
        attv[i] = att[lane + 32 * i];
    }

    float m = -INFINITY;
    float denom = 0.f;
    float acc[4] = {0.f, 0.f, 0.f, 0.f};
    for (int p = s0; p < s1; p++) {
        int src = g_csr_src[p];
        const float* row = xl + src * 128;
        float rowv[4];
        float logit = 0.f;
#pragma unroll
        for (int i = 0; i < 4; i++) {
            rowv[i] = row[lane + 32 * i];
            float v = rowv[i] + xrv[i];
            float lr = v > 0.f ? v : SLOPE * v;
            logit += lr * attv[i];
        }
#pragma unroll
        for (int o = 16; o; o >>= 1) logit += __shfl_xor_sync(0xffffffffu, logit, o);
        float pe;
        if (logit > m) {                 // warp-uniform branch
            float sc = expf(m - logit);  // first edge: exp(-inf)=0
            denom *= sc;
#pragma unroll
            for (int i = 0; i < 4; i++) acc[i] *= sc;
            m = logit;
            pe = 1.f;
        } else {
            pe = expf(logit - m);
        }
        denom += pe;
#pragma unroll
        for (int i = 0; i < 4; i++) acc[i] += pe * rowv[i];
    }

    float inv = (s1 > s0) ? 1.f / denom : 0.f;
#pragma unroll
    for (int i = 0; i < 4; i++) {
        int f = lane + 32 * i;
        float o = acc[i] * inv + bias[f];
        if (do_bn) {
            float sc = gamma[f] * rsqrtf(var[f] + BN_EPS);
            o = (o - mean[f]) * sc + beta[f];
            o = fmaxf(o, 0.f);
        }
        out[d * 128 + f] = o;
    }
}

// ---------------- pooling: block per graph (batch is sorted) ----------------
__global__ void k_pool() {
    int g = blockIdx.x;
    int t = threadIdx.x;   // 128
    int s = g_gstart[g], e = g_gstart[g + 1];
    float sum = 0.f;
    for (int r = s; r < e; r++) sum += g_h2[r * 128 + t];
    int cnt = e - s;
    g_pooled[g * 128 + t] = sum / (float)(cnt > 0 ? cnt : 1);
}

// ---------------- fused head: fc1(+bias,relu) tile + fc3 + sigmoid ----------------
__global__ void k_head(const float* __restrict__ fc1w, const float* __restrict__ fc1b,
                       const float* __restrict__ fc3w, const float* __restrict__ fc3b,
                       float* __restrict__ out) {
    __shared__ float As[16][65];
    __shared__ float Bs[16][64];
    __shared__ float red[64][17];
    int t = threadIdx.x;
    int tx = t & 15, ty = t >> 4;
    int g0 = blockIdx.x * 64;
    int s = blockIdx.y;           // stock
    int colBase = s * 64;
    float acc[4][4] = {};
    for (int k0 = 0; k0 < 128; k0 += 16) {
#pragma unroll
        for (int i = 0; i < 4; i++) {
            int e = t + i * 256;
            int r = e >> 4, kk = e & 15;
            int gg = g0 + r;
            As[kk][r] = (gg < Gg) ? g_pooled[gg * 128 + k0 + kk] : 0.f;
        }
#pragma unroll
        for (int i = 0; i < 4; i++) {
            int e = t + i * 256;
            int kk = e >> 6, c = e & 63;
            Bs[kk][c] = fc1w[(k0 + kk) * (NSs * M0) + colBase + c];
        }
        __syncthreads();
#pragma unroll
        for (int kk = 0; kk < 16; kk++) {
            float a[4], b[4];
#pragma unroll
            for (int r = 0; r < 4; r++) a[r] = As[kk][ty * 4 + r];
#pragma unroll
            for (int c = 0; c < 4; c++) b[c] = Bs[kk][tx * 4 + c];
#pragma unroll
            for (int r = 0; r < 4; r++)
#pragma unroll
                for (int c = 0; c < 4; c++) acc[r][c] += a[r] * b[c];
        }
        __syncthreads();
    }
#pragma unroll
    for (int r = 0; r < 4; r++) {
        float p = 0.f;
#pragma unroll
        for (int c = 0; c < 4; c++) {
            int j = tx * 4 + c;
            float v = acc[r][c] + fc1b[colBase + j];
            v = fmaxf(v, 0.f);
            p += v * fc3w[j];
        }
        red[ty * 4 + r][tx] = p;
    }
    __syncthreads();
    if (t < 64) {
        float v = 0.f;
#pragma unroll
        for (int i = 0; i < 16; i++) v += red[t][i];
        v += fc3b[0];
        float o = 1.f / (1.f + expf(-v));
        int g = g0 + t;
        if (g < Gg) out[g * NSs + s] = o;
    }
}

// ---------------- launch ----------------
extern "C" void kernel_launch(void* const* d_in, const int* in_sizes, int n_in,
                              void* d_out, int out_size) {
    const float* x     = (const float*)d_in[0];
    const int*   gd    = (const int*)d_in[1];
    const int*   batch = (const int*)d_in[2];
    const float* wl0   = (const float*)d_in[3];
    const float* bl0   = (const float*)d_in[4];
    const float* wr0   = (const float*)d_in[5];
    const float* br0   = (const float*)d_in[6];
    const float* att0  = (const float*)d_in[7];
    const float* b0    = (const float*)d_in[8];
    const float* wl1   = (const float*)d_in[9];
    const float* bl1   = (const float*)d_in[10];
    const float* wr1   = (const float*)d_in[11];
    const float* br1   = (const float*)d_in[12];
    const float* att1  = (const float*)d_in[13];
    const float* b1    = (const float*)d_in[14];
    const float* bn_g  = (const float*)d_in[15];
    const float* bn_b  = (const float*)d_in[16];
    const float* bn_m  = (const float*)d_in[17];
    const float* bn_v  = (const float*)d_in[18];
    const float* fc1w  = (const float*)d_in[19];
    const float* fc1b  = (const float*)d_in[20];
    const float* fc3w  = (const float*)d_in[21];
    const float* fc3b  = (const float*)d_in[22];
    float* out = (float*)d_out;

    // real device addresses (NOT the host shadow symbols)
    float *p_xl, *p_xr, *p_h1, *p_h2;
    cudaGetSymbolAddress((void**)&p_xl, g_xl);
    cudaGetSymbolAddress((void**)&p_xr, g_xr);
    cudaGetSymbolAddress((void**)&p_h1, g_h1);
    cudaGetSymbolAddress((void**)&p_h2, g_h2);

    // CSR build + graph ranges
    k_decode_zero<<<(Ee + 255) / 256, 256>>>(gd);
    k_hist<<<(Ee + 255) / 256, 256>>>(batch);
    k_scan1<<<SCAN_NB, SCAN_BLK>>>();
    k_scan2_gscan<<<2, 32>>>();
    k_scan3<<<(Nn + 255) / 256, 256>>>();
    k_fill<<<(Ee + 255) / 256, 256>>>();

    const int GB = (Nn + 63) / 64;   // 782
    // layer 0
    k_gemm_tc<<<GB, 256>>>(x, wl0, bl0, p_xl, Nn);
    k_gemm_tc<<<GB, 256>>>(x, wr0, br0, p_xr, Nn);
    k_aggregate<<<(Nn * 32 + 255) / 256, 256>>>(p_xl, p_xr, att0, b0, p_h1,
                                                1, bn_g, bn_b, bn_m, bn_v);
    // layer 1
    k_gemm_tc<<<GB, 256>>>(p_h1, wl1, bl1, p_xl, Nn);
    k_gemm_tc<<<GB, 256>>>(p_h1, wr1, br1, p_xr, Nn);
    k_aggregate<<<(Nn * 32 + 255) / 256, 256>>>(p_xl, p_xr, att1, b1, p_h2,
                                                0, (const float*)0, (const float*)0,
                                                (const float*)0, (const float*)0);
    // pool + head
    k_pool<<<Gg, 128>>>();
    dim3 hgrid((Gg + 63) / 64, NSs);
    k_head<<<hgrid, 256>>>(fc1w, fc1b, fc3w, fc3b, out);
    (void)in_sizes; (void)n_in; (void)out_size;
}

// round 9
// speedup vs baseline: 1.1971x; 1.1971x over previous
#include <cuda_runtime.h>
#include <mma.h>
#include <math.h>

using namespace nvcuda;

#define Nn 50000
#define Ee 800000
#define Dd 128
#define Gg 500
#define NSs 100
#define M0 64
#define SLOPE 0.2f
#define BN_EPS 1e-5f

#define SCAN_BLK 512
#define SCAN_NB ((Nn + SCAN_BLK - 1) / SCAN_BLK)   // 98

// -------- scratch (device globals; no allocation allowed) --------
// NEVER pass these names from host code directly (host shadow + ATS trap);
// always cudaGetSymbolAddress.
__device__ float g_xl[Nn * Dd];
__device__ float g_xr[Nn * Dd];
__device__ float g_h1[Nn * Dd];
__device__ float g_h2[Nn * Dd];
__device__ float g_pooled[Gg * Dd];
__device__ int   g_src[Ee];
__device__ int   g_dst[Ee];
__device__ int   g_counts[Nn];
__device__ int   g_incl[Nn];
__device__ int   g_rowPtr[Nn + 1];
__device__ int   g_head[Nn];
__device__ int   g_csr_src[Ee];
__device__ int   g_blockSums[SCAN_NB + 8];
__device__ int   g_blockOff[SCAN_NB + 8];
__device__ int   g_gcounts[Gg];
__device__ int   g_gstart[Gg + 1];

// ---------------- decode + zero (merged; grid covers Ee >= Nn) ----------------
__global__ void k_decode_zero(const int* __restrict__ gd) {
    int i = blockIdx.x * blockDim.x + threadIdx.x;
    if (i < Nn) g_counts[i] = 0;
    if (i < Gg) g_gcounts[i] = 0;
    if (i >= Ee) return;
    bool w64 = (gd[1] == 0 && gd[3] == 0 && gd[5] == 0 && gd[7] == 0);
    if (w64) {
        g_src[i] = gd[2 * i];
        g_dst[i] = gd[2 * Ee + 2 * i];
    } else {
        g_src[i] = gd[i];
        g_dst[i] = gd[Ee + i];
    }
}

// ---------------- both histograms (merged) ----------------
__global__ void k_hist(const int* __restrict__ batch) {
    int i = blockIdx.x * blockDim.x + threadIdx.x;
    if (i < Ee) atomicAdd(&g_counts[g_dst[i]], 1);
    if (i < Nn) atomicAdd(&g_gcounts[batch[i]], 1);
}

// ---------------- scan (counts -> rowPtr) ----------------
__global__ void k_scan1() {
    __shared__ int s[SCAN_BLK];
    int tid = threadIdx.x;
    int i = blockIdx.x * SCAN_BLK + tid;
    int v = (i < Nn) ? g_counts[i] : 0;
    s[tid] = v;
    __syncthreads();
    for (int off = 1; off < SCAN_BLK; off <<= 1) {
        int add = (tid >= off) ? s[tid - off] : 0;
        __syncthreads();
        s[tid] += add;
        __syncthreads();
    }
    if (i < Nn) g_incl[i] = s[tid];
    if (tid == SCAN_BLK - 1) g_blockSums[blockIdx.x] = s[tid];
}
// one 512-thread block: parallel scan of blockSums AND graph counts
__global__ void k_scan2p() {
    __shared__ int s[512];
    int t = threadIdx.x;
    // phase 1: blockSums[SCAN_NB] -> exclusive blockOff
    int v = (t < SCAN_NB) ? g_blockSums[t] : 0;
    s[t] = v;
    __syncthreads();
    for (int off = 1; off < 512; off <<= 1) {
        int a = (t >= off) ? s[t - off] : 0;
        __syncthreads();
        s[t] += a;
        __syncthreads();
    }
    if (t < SCAN_NB) g_blockOff[t] = s[t] - v;
    __syncthreads();
    // phase 2: gcounts[Gg] -> exclusive gstart (+ total)
    int w = (t < Gg) ? g_gcounts[t] : 0;
    s[t] = w;
    __syncthreads();
    for (int off = 1; off < 512; off <<= 1) {
        int a = (t >= off) ? s[t - off] : 0;
        __syncthreads();
        s[t] += a;
        __syncthreads();
    }
    if (t < Gg) g_gstart[t] = s[t] - w;
    if (t == Gg - 1) g_gstart[Gg] = s[t];
}
__global__ void k_scan3() {
    int i = blockIdx.x * blockDim.x + threadIdx.x;
    if (i < Nn) {
        int tot = g_incl[i] + g_blockOff[i / SCAN_BLK];
        int excl = tot - g_counts[i];
        g_rowPtr[i] = excl;
        g_head[i] = excl;
        if (i == Nn - 1) g_rowPtr[Nn] = tot;
    }
}
__global__ void k_fill() {
    int i = blockIdx.x * blockDim.x + threadIdx.x;
    if (i < Ee) {
        int pos = atomicAdd(&g_head[g_dst[i]], 1);
        g_csr_src[pos] = g_src[i];
    }
}

// ---------------- tensor-core node GEMM (3xTF32): C[nrows,128] = A @ W + bias --------
// (unchanged from round 8 — this is the profiling target at launch index 3)
__global__ void k_gemm_tc(const float* __restrict__ A, const float* __restrict__ W,
                          const float* __restrict__ bias, float* __restrict__ C,
                          int nrows) {
    __shared__ float sm[8192];
    float* As = sm;
    float* Bs = sm + 2048;
    int tid = threadIdx.x;
    int wid = tid >> 5;
    int warp_m = wid >> 1;
    int warp_n = wid & 1;
    int rowBase = blockIdx.x * 64;

    wmma::fragment<wmma::accumulator, 16, 16, 8, float> acc[4];
#pragma unroll
    for (int i = 0; i < 4; i++) wmma::fill_fragment(acc[i], 0.f);

    for (int k0 = 0; k0 < 128; k0 += 32) {
        __syncthreads();
#pragma unroll
        for (int i = 0; i < 2; i++) {
            int idx = tid + i * 256;
            int r = idx >> 3, c4 = idx & 7;
            int gr = rowBase + r;
            float4 v = make_float4(0.f, 0.f, 0.f, 0.f);
            if (gr < nrows) v = *(const float4*)(A + gr * 128 + k0 + c4 * 4);
            *(float4*)(As + r * 32 + c4 * 4) = v;
        }
#pragma unroll
        for (int i = 0; i < 4; i++) {
            int idx = tid + i * 256;
            int r = idx >> 5, c4 = idx & 31;
            *(float4*)(Bs + r * 128 + c4 * 4) =
                *(const float4*)(W + (k0 + r) * 128 + c4 * 4);
        }
        __syncthreads();
#pragma unroll
        for (int kk = 0; kk < 32; kk += 8) {
            wmma::fragment<wmma::matrix_a, 16, 16, 8, wmma::precision::tf32, wmma::row_major> af, ah, al;
            wmma::load_matrix_sync(af, As + warp_m * 16 * 32 + kk, 32);
#pragma unroll
            for (int e = 0; e < af.num_elements; e++) {
                float v = af.x[e];
                float hi = wmma::__float_to_tf32(v);
                ah.x[e] = hi;
                al.x[e] = wmma::__float_to_tf32(v - hi);
            }
#pragma unroll
            for (int nt = 0; nt < 4; nt++) {
                wmma::fragment<wmma::matrix_b, 16, 16, 8, wmma::precision::tf32, wmma::row_major> bf, bh, bl;
                wmma::load_matrix_sync(bf, Bs + kk * 128 + warp_n * 64 + nt * 16, 128);
#pragma unroll
                for (int e = 0; e < bf.num_elements; e++) {
                    float v = bf.x[e];
                    float hi = wmma::__float_to_tf32(v);
                    bh.x[e] = hi;
                    bl.x[e] = wmma::__float_to_tf32(v - hi);
                }
                wmma::mma_sync(acc[nt], al, bh, acc[nt]);
                wmma::mma_sync(acc[nt], ah, bl, acc[nt]);
                wmma::mma_sync(acc[nt], ah, bh, acc[nt]);
            }
        }
    }
    __syncthreads();
#pragma unroll
    for (int nt = 0; nt < 4; nt++)
        wmma::store_matrix_sync(sm + warp_m * 16 * 128 + warp_n * 64 + nt * 16,
                                acc[nt], 128, wmma::mem_row_major);
    __syncthreads();
#pragma unroll
    for (int i = 0; i < 8; i++) {
        int idx = tid + i * 256;
        int r = idx >> 5, c4 = idx & 31;
        int gr = rowBase + r;
        if (gr < nrows) {
            float4 v = *(float4*)(sm + r * 128 + c4 * 4);
            float4 bv = *(const float4*)(bias + c4 * 4);
            v.x += bv.x; v.y += bv.y; v.z += bv.z; v.w += bv.w;
            *(float4*)(C + gr * 128 + c4 * 4) = v;
        }
    }
}

// ---------------- GATv2 aggregate: warp/node, float4 gathers, 2-edge pipeline -------
__device__ __forceinline__ float edge_partial(float4 r, float4 xrv, float4 attv) {
    float vx = r.x + xrv.x, vy = r.y + xrv.y, vz = r.z + xrv.z, vw = r.w + xrv.w;
    vx = vx > 0.f ? vx : SLOPE * vx;
    vy = vy > 0.f ? vy : SLOPE * vy;
    vz = vz > 0.f ? vz : SLOPE * vz;
    vw = vw > 0.f ? vw : SLOPE * vw;
    return vx * attv.x + vy * attv.y + vz * attv.z + vw * attv.w;
}
__device__ __forceinline__ void online_update(float l, float4 r, float& m,
                                              float& denom, float4& acc) {
    if (l > m) {                     // warp-uniform (l identical across lanes)
        float sc = __expf(m - l);    // first edge: __expf(-inf)=0
        denom = denom * sc + 1.f;
        acc.x = acc.x * sc + r.x;
        acc.y = acc.y * sc + r.y;
        acc.z = acc.z * sc + r.z;
        acc.w = acc.w * sc + r.w;
        m = l;
    } else {
        float pe = __expf(l - m);
        denom += pe;
        acc.x += pe * r.x;
        acc.y += pe * r.y;
        acc.z += pe * r.z;
        acc.w += pe * r.w;
    }
}
__global__ void k_aggregate(const float4* __restrict__ xl, const float4* __restrict__ xr,
                            const float4* __restrict__ att, const float4* __restrict__ bias,
                            float4* __restrict__ out,
                            int do_bn,
                            const float4* __restrict__ gamma, const float4* __restrict__ beta,
                            const float4* __restrict__ mean, const float4* __restrict__ var) {
    int warpId = (blockIdx.x * blockDim.x + threadIdx.x) >> 5;
    if (warpId >= Nn) return;
    int lane = threadIdx.x & 31;
    int d = warpId;
    int s0 = g_rowPtr[d], s1 = g_rowPtr[d + 1];

    float4 xrv = xr[d * 32 + lane];
    float4 attv = att[lane];

    float m = -INFINITY;
    float denom = 0.f;
    float4 acc = make_float4(0.f, 0.f, 0.f, 0.f);

    int p = s0;
    for (; p + 2 <= s1; p += 2) {
        int i0 = g_csr_src[p];
        int i1 = g_csr_src[p + 1];
        float4 r0 = xl[i0 * 32 + lane];   // independent 128-bit gathers (MLP 2)
        float4 r1 = xl[i1 * 32 + lane];
        float l0 = edge_partial(r0, xrv, attv);
        float l1 = edge_partial(r1, xrv, attv);
#pragma unroll
        for (int o = 16; o; o >>= 1) {    // two interleaved reduction trees
            l0 += __shfl_xor_sync(0xffffffffu, l0, o);
            l1 += __shfl_xor_sync(0xffffffffu, l1, o);
        }
        online_update(l0, r0, m, denom, acc);
        online_update(l1, r1, m, denom, acc);
    }
    if (p < s1) {
        int i0 = g_csr_src[p];
        float4 r0 = xl[i0 * 32 + lane];
        float l0 = edge_partial(r0, xrv, attv);
#pragma unroll
        for (int o = 16; o; o >>= 1) l0 += __shfl_xor_sync(0xffffffffu, l0, o);
        online_update(l0, r0, m, denom, acc);
    }

    float inv = (s1 > s0) ? 1.f / denom : 0.f;
    float4 bv = bias[lane];
    float4 o;
    o.x = acc.x * inv + bv.x;
    o.y = acc.y * inv + bv.y;
    o.z = acc.z * inv + bv.z;
    o.w = acc.w * inv + bv.w;
    if (do_bn) {
        float4 gv = gamma[lane], be = beta[lane], mv = mean[lane], vv = var[lane];
        o.x = fmaxf(gv.x * (o.x - mv.x) * rsqrtf(vv.x + BN_EPS) + be.x, 0.f);
        o.y = fmaxf(gv.y * (o.y - mv.y) * rsqrtf(vv.y + BN_EPS) + be.y, 0.f);
        o.z = fmaxf(gv.z * (o.z - mv.z) * rsqrtf(vv.z + BN_EPS) + be.z, 0.f);
        o.w = fmaxf(gv.w * (o.w - mv.w) * rsqrtf(vv.w + BN_EPS) + be.w, 0.f);
    }
    out[d * 32 + lane] = o;
}

// ---------------- pooling: block per graph (batch is sorted) ----------------
__global__ void k_pool() {
    int g = blockIdx.x;
    int t = threadIdx.x;   // 128
    int s = g_gstart[g], e = g_gstart[g + 1];
    float sum = 0.f;
    for (int r = s; r < e; r++) sum += g_h2[r * 128 + t];
    int cnt = e - s;
    g_pooled[g * 128 + t] = sum / (float)(cnt > 0 ? cnt : 1);
}

// ---------------- fused head: fc1(+bias,relu) tile + fc3 + sigmoid ----------------
__global__ void k_head(const float* __restrict__ fc1w, const float* __restrict__ fc1b,
                       const float* __restrict__ fc3w, const float* __restrict__ fc3b,
                       float* __restrict__ out) {
    __shared__ float As[16][65];
    __shared__ float Bs[16][64];
    __shared__ float red[64][17];
    int t = threadIdx.x;
    int tx = t & 15, ty = t >> 4;
    int g0 = blockIdx.x * 64;
    int s = blockIdx.y;
    int colBase = s * 64;
    float acc[4][4] = {};
    for (int k0 = 0; k0 < 128; k0 += 16) {
#pragma unroll
        for (int i = 0; i < 4; i++) {
            int e = t + i * 256;
            int r = e >> 4, kk = e & 15;
            int gg = g0 + r;
            As[kk][r] = (gg < Gg) ? g_pooled[gg * 128 + k0 + kk] : 0.f;
        }
#pragma unroll
        for (int i = 0; i < 4; i++) {
            int e = t + i * 256;
            int kk = e >> 6, c = e & 63;
            Bs[kk][c] = fc1w[(k0 + kk) * (NSs * M0) + colBase + c];
        }
        __syncthreads();
#pragma unroll
        for (int kk = 0; kk < 16; kk++) {
            float a[4], b[4];
#pragma unroll
            for (int r = 0; r < 4; r++) a[r] = As[kk][ty * 4 + r];
#pragma unroll
            for (int c = 0; c < 4; c++) b[c] = Bs[kk][tx * 4 + c];
#pragma unroll
            for (int r = 0; r < 4; r++)
#pragma unroll
                for (int c = 0; c < 4; c++) acc[r][c] += a[r] * b[c];
        }
        __syncthreads();
    }
#pragma unroll
    for (int r = 0; r < 4; r++) {
        float p = 0.f;
#pragma unroll
        for (int c = 0; c < 4; c++) {
            int j = tx * 4 + c;
            float v = acc[r][c] + fc1b[colBase + j];
            v = fmaxf(v, 0.f);
            p += v * fc3w[j];
        }
        red[ty * 4 + r][tx] = p;
    }
    __syncthreads();
    if (t < 64) {
        float v = 0.f;
#pragma unroll
        for (int i = 0; i < 16; i++) v += red[t][i];
        v += fc3b[0];
        float o = 1.f / (1.f + expf(-v));
        int g = g0 + t;
        if (g < Gg) out[g * NSs + s] = o;
    }
}

// ---------------- launch ----------------
extern "C" void kernel_launch(void* const* d_in, const int* in_sizes, int n_in,
                              void* d_out, int out_size) {
    const float* x     = (const float*)d_in[0];
    const int*   gd    = (const int*)d_in[1];
    const int*   batch = (const int*)d_in[2];
    const float* wl0   = (const float*)d_in[3];
    const float* bl0   = (const float*)d_in[4];
    const float* wr0   = (const float*)d_in[5];
    const float* br0   = (const float*)d_in[6];
    const float* att0  = (const float*)d_in[7];
    const float* b0    = (const float*)d_in[8];
    const float* wl1   = (const float*)d_in[9];
    const float* bl1   = (const float*)d_in[10];
    const float* wr1   = (const float*)d_in[11];
    const float* br1   = (const float*)d_in[12];
    const float* att1  = (const float*)d_in[13];
    const float* b1    = (const float*)d_in[14];
    const float* bn_g  = (const float*)d_in[15];
    const float* bn_b  = (const float*)d_in[16];
    const float* bn_m  = (const float*)d_in[17];
    const float* bn_v  = (const float*)d_in[18];
    const float* fc1w  = (const float*)d_in[19];
    const float* fc1b  = (const float*)d_in[20];
    const float* fc3w  = (const float*)d_in[21];
    const float* fc3b  = (const float*)d_in[22];
    float* out = (float*)d_out;

    // real device addresses (NOT the host shadow symbols)
    float *p_xl, *p_xr, *p_h1, *p_h2;
    cudaGetSymbolAddress((void**)&p_xl, g_xl);
    cudaGetSymbolAddress((void**)&p_xr, g_xr);
    cudaGetSymbolAddress((void**)&p_h1, g_h1);
    cudaGetSymbolAddress((void**)&p_h2, g_h2);

    const int GB = (Nn + 63) / 64;   // 782

    // launch order chosen so index 3 (ncu's capture slot) = first GEMM
    k_decode_zero<<<(Ee + 255) / 256, 256>>>(gd);                       // 0
    k_hist<<<(Ee + 255) / 256, 256>>>(batch);                           // 1
    k_scan1<<<SCAN_NB, SCAN_BLK>>>();                                   // 2
    k_gemm_tc<<<GB, 256>>>(x, wl0, bl0, p_xl, Nn);                      // 3  <- profiled
    k_gemm_tc<<<GB, 256>>>(x, wr0, br0, p_xr, Nn);                      // 4
    k_scan2p<<<1, 512>>>();                                             // 5
    k_scan3<<<(Nn + 255) / 256, 256>>>();                               // 6
    k_fill<<<(Ee + 255) / 256, 256>>>();                                // 7
    k_aggregate<<<(Nn * 32 + 255) / 256, 256>>>(                        // 8
        (const float4*)p_xl, (const float4*)p_xr,
        (const float4*)att0, (const float4*)b0, (float4*)p_h1,
        1, (const float4*)bn_g, (const float4*)bn_b,
        (const float4*)bn_m, (const float4*)bn_v);
    k_gemm_tc<<<GB, 256>>>(p_h1, wl1, bl1, p_xl, Nn);                   // 9
    k_gemm_tc<<<GB, 256>>>(p_h1, wr1, br1, p_xr, Nn);                   // 10
    k_aggregate<<<(Nn * 32 + 255) / 256, 256>>>(                        // 11
        (const float4*)p_xl, (const float4*)p_xr,
        (const float4*)att1, (const float4*)b1, (float4*)p_h2,
        0, (const float4*)0, (const float4*)0,
        (const float4*)0, (const float4*)0);
    k_pool<<<Gg, 128>>>();                                              // 12
    dim3 hgrid((Gg + 63) / 64, NSs);
    k_head<<<hgrid, 256>>>(fc1w, fc1b, fc3w, fc3b, out);                // 13
    (void)in_sizes; (void)n_in; (void)out_size;
}

// round 10
// speedup vs baseline: 1.2986x; 1.0848x over previous
#include <cuda_runtime.h>
#include <mma.h>
#include <math.h>

using namespace nvcuda;

#define Nn 50000
#define Ee 800000
#define Dd 128
#define Gg 500
#define NSs 100
#define M0 64
#define SLOPE 0.2f
#define BN_EPS 1e-5f

#define SCAN_BLK 512
#define SCAN_NB ((Nn + SCAN_BLK - 1) / SCAN_BLK)   // 98

__device__ __forceinline__ float tf32r(float x) {
    float r;
    asm("cvt.rna.tf32.f32 %0, %1;" : "=f"(r) : "f"(x));
    return r;
}

// -------- scratch (device globals; no allocation allowed) --------
// NEVER pass these names from host code directly (host shadow + ATS trap);
// always cudaGetSymbolAddress.
__device__ float g_xl[Nn * Dd];
__device__ float g_xr[Nn * Dd];
__device__ float g_h1[Nn * Dd];
__device__ float g_h2[Nn * Dd];
__device__ float g_pooled[Gg * Dd];
__device__ int   g_src[Ee];
__device__ int   g_dst[Ee];
__device__ int   g_counts[Nn];
__device__ int   g_incl[Nn];
__device__ int   g_rowPtr[Nn + 1];
__device__ int   g_head[Nn];
__device__ int   g_csr_src[Ee];
__device__ int   g_blockSums[SCAN_NB + 8];
__device__ int   g_blockOff[SCAN_NB + 8];
__device__ int   g_gcounts[Gg];
__device__ int   g_gstart[Gg + 1];

// ---------------- decode + zero (merged) ----------------
__global__ void k_decode_zero(const int* __restrict__ gd) {
    int i = blockIdx.x * blockDim.x + threadIdx.x;
    if (i < Nn) g_counts[i] = 0;
    if (i < Gg) g_gcounts[i] = 0;
    if (i >= Ee) return;
    bool w64 = (gd[1] == 0 && gd[3] == 0 && gd[5] == 0 && gd[7] == 0);
    if (w64) {
        g_src[i] = gd[2 * i];
        g_dst[i] = gd[2 * Ee + 2 * i];
    } else {
        g_src[i] = gd[i];
        g_dst[i] = gd[Ee + i];
    }
}

// ---------------- both histograms (merged) ----------------
__global__ void k_hist(const int* __restrict__ batch) {
    int i = blockIdx.x * blockDim.x + threadIdx.x;
    if (i < Ee) atomicAdd(&g_counts[g_dst[i]], 1);
    if (i < Nn) atomicAdd(&g_gcounts[batch[i]], 1);
}

// ---------------- scans ----------------
__global__ void k_scan1() {
    __shared__ int s[SCAN_BLK];
    int tid = threadIdx.x;
    int i = blockIdx.x * SCAN_BLK + tid;
    int v = (i < Nn) ? g_counts[i] : 0;
    s[tid] = v;
    __syncthreads();
    for (int off = 1; off < SCAN_BLK; off <<= 1) {
        int add = (tid >= off) ? s[tid - off] : 0;
        __syncthreads();
        s[tid] += add;
        __syncthreads();
    }
    if (i < Nn) g_incl[i] = s[tid];
    if (tid == SCAN_BLK - 1) g_blockSums[blockIdx.x] = s[tid];
}
__global__ void k_scan2p() {
    __shared__ int s[512];
    int t = threadIdx.x;
    int v = (t < SCAN_NB) ? g_blockSums[t] : 0;
    s[t] = v;
    __syncthreads();
    for (int off = 1; off < 512; off <<= 1) {
        int a = (t >= off) ? s[t - off] : 0;
        __syncthreads();
        s[t] += a;
        __syncthreads();
    }
    if (t < SCAN_NB) g_blockOff[t] = s[t] - v;
    __syncthreads();
    int w = (t < Gg) ? g_gcounts[t] : 0;
    s[t] = w;
    __syncthreads();
    for (int off = 1; off < 512; off <<= 1) {
        int a = (t >= off) ? s[t - off] : 0;
        __syncthreads();
        s[t] += a;
        __syncthreads();
    }
    if (t < Gg) g_gstart[t] = s[t] - w;
    if (t == Gg - 1) g_gstart[Gg] = s[t];
}
__global__ void k_scan3() {
    int i = blockIdx.x * blockDim.x + threadIdx.x;
    if (i < Nn) {
        int tot = g_incl[i] + g_blockOff[i / SCAN_BLK];
        int excl = tot - g_counts[i];
        g_rowPtr[i] = excl;
        g_head[i] = excl;
        if (i == Nn - 1) g_rowPtr[Nn] = tot;
    }
}
__global__ void k_fill() {
    int i = blockIdx.x * blockDim.x + threadIdx.x;
    if (i < Ee) {
        int pos = atomicAdd(&g_head[g_dst[i]], 1);
        g_csr_src[pos] = g_src[i];
    }
}

// ---------------- fused dual GEMM (plain TF32): C0 = A@W0+b0, C1 = A@W1+b1 ------
// block = 64 rows; A (64x128, tf32-rounded) staged in smem ONCE; each weight
// streamed through a 32x128 B buffer; epilogue staged through B buffer in two
// 32-row chunks. 8 warps: warp_m = wid>>1 (16-row band), warp_n = wid&1 (64 cols).
__global__ void k_gemm_dual(const float* __restrict__ A,
                            const float* __restrict__ W0, const float* __restrict__ bias0,
                            float* __restrict__ C0,
                            const float* __restrict__ W1, const float* __restrict__ bias1,
                            float* __restrict__ C1,
                            int nrows) {
    __shared__ float sA[64 * 128];   // 32 KB
    __shared__ float sB[32 * 128];   // 16 KB (B chunk / epilogue staging)
    int tid = threadIdx.x;
    int wid = tid >> 5;
    int warp_m = wid >> 1;           // 0..3
    int warp_n = wid & 1;            // 0..1
    int rowBase = blockIdx.x * 64;

    // stage A once (tf32-rounded at staging; inner loop has NO conversions)
#pragma unroll
    for (int i = 0; i < 8; i++) {
        int idx = tid + i * 256;                 // 0..2047 float4 units
        int r = idx >> 5, c4 = idx & 31;
        int gr = rowBase + r;
        float4 v = make_float4(0.f, 0.f, 0.f, 0.f);
        if (gr < nrows) v = *(const float4*)(A + gr * 128 + c4 * 4);
        v.x = tf32r(v.x); v.y = tf32r(v.y); v.z = tf32r(v.z); v.w = tf32r(v.w);
        *(float4*)(sA + r * 128 + c4 * 4) = v;
    }

#pragma unroll
    for (int w = 0; w < 2; w++) {
        const float* Wp = w ? W1 : W0;
        const float* bp = w ? bias1 : bias0;
        float* Cp = w ? C1 : C0;

        wmma::fragment<wmma::accumulator, 16, 16, 8, float> acc[4];
#pragma unroll
        for (int i = 0; i < 4; i++) wmma::fill_fragment(acc[i], 0.f);

        for (int k0 = 0; k0 < 128; k0 += 32) {
            __syncthreads();
            // stage B 32x128 (tf32-rounded)
#pragma unroll
            for (int i = 0; i < 4; i++) {
                int idx = tid + i * 256;          // 0..1023 float4 units
                int r = idx >> 5, c4 = idx & 31;
                float4 v = *(const float4*)(Wp + (k0 + r) * 128 + c4 * 4);
                v.x = tf32r(v.x); v.y = tf32r(v.y); v.z = tf32r(v.z); v.w = tf32r(v.w);
                *(float4*)(sB + r * 128 + c4 * 4) = v;
            }
            __syncthreads();
#pragma unroll
            for (int kk = 0; kk < 32; kk += 8) {
                wmma::fragment<wmma::matrix_a, 16, 16, 8, wmma::precision::tf32, wmma::row_major> af;
                wmma::load_matrix_sync(af, sA + warp_m * 16 * 128 + k0 + kk, 128);
#pragma unroll
                for (int nt = 0; nt < 4; nt++) {
                    wmma::fragment<wmma::matrix_b, 16, 16, 8, wmma::precision::tf32, wmma::row_major> bf;
                    wmma::load_matrix_sync(bf, sB + kk * 128 + warp_n * 64 + nt * 16, 128);
                    wmma::mma_sync(acc[nt], af, bf, acc[nt]);
                }
            }
        }

        // epilogue: two 32-row chunks through sB
#pragma unroll
        for (int half = 0; half < 2; half++) {
            __syncthreads();
            if ((warp_m >> 1) == half) {
                int lm = warp_m & 1;     // 0..1 within this 32-row chunk
#pragma unroll
                for (int nt = 0; nt < 4; nt++)
                    wmma::store_matrix_sync(sB + lm * 16 * 128 + warp_n * 64 + nt * 16,
                                            acc[nt], 128, wmma::mem_row_major);
            }
            __syncthreads();
#pragma unroll
            for (int i = 0; i < 4; i++) {
                int idx = tid + i * 256;          // 0..1023 float4 units (32x128)
                int r = idx >> 5, c4 = idx & 31;
                int gr = rowBase + half * 32 + r;
                if (gr < nrows) {
                    float4 v = *(float4*)(sB + r * 128 + c4 * 4);
                    float4 bv = *(const float4*)(bp + c4 * 4);
                    v.x += bv.x; v.y += bv.y; v.z += bv.z; v.w += bv.w;
                    *(float4*)(Cp + gr * 128 + c4 * 4) = v;
                }
            }
        }
    }
}

// ---------------- GATv2 aggregate: warp/node, float4 gathers, 2-edge pipeline -------
__device__ __forceinline__ float edge_partial(float4 r, float4 xrv, float4 attv) {
    float vx = r.x + xrv.x, vy = r.y + xrv.y, vz = r.z + xrv.z, vw = r.w + xrv.w;
    vx = vx > 0.f ? vx : SLOPE * vx;
    vy = vy > 0.f ? vy : SLOPE * vy;
    vz = vz > 0.f ? vz : SLOPE * vz;
    vw = vw > 0.f ? vw : SLOPE * vw;
    return vx * attv.x + vy * attv.y + vz * attv.z + vw * attv.w;
}
__device__ __forceinline__ void online_update(float l, float4 r, float& m,
                                              float& denom, float4& acc) {
    if (l > m) {
        float sc = __expf(m - l);
        denom = denom * sc + 1.f;
        acc.x = acc.x * sc + r.x;
        acc.y = acc.y * sc + r.y;
        acc.z = acc.z * sc + r.z;
        acc.w = acc.w * sc + r.w;
        m = l;
    } else {
        float pe = __expf(l - m);
        denom += pe;
        acc.x += pe * r.x;
        acc.y += pe * r.y;
        acc.z += pe * r.z;
        acc.w += pe * r.w;
    }
}
__global__ void k_aggregate(const float4* __restrict__ xl, const float4* __restrict__ xr,
                            const float4* __restrict__ att, const float4* __restrict__ bias,
                            float4* __restrict__ out,
                            int do_bn,
                            const float4* __restrict__ gamma, const float4* __restrict__ beta,
                            const float4* __restrict__ mean, const float4* __restrict__ var) {
    int warpId = (blockIdx.x * blockDim.x + threadIdx.x) >> 5;
    if (warpId >= Nn) return;
    int lane = threadIdx.x & 31;
    int d = warpId;
    int s0 = g_rowPtr[d], s1 = g_rowPtr[d + 1];

    float4 xrv = xr[d * 32 + lane];
    float4 attv = att[lane];

    float m = -INFINITY;
    float denom = 0.f;
    float4 acc = make_float4(0.f, 0.f, 0.f, 0.f);

    int p = s0;
    for (; p + 2 <= s1; p += 2) {
        int i0 = g_csr_src[p];
        int i1 = g_csr_src[p + 1];
        float4 r0 = xl[i0 * 32 + lane];
        float4 r1 = xl[i1 * 32 + lane];
        float l0 = edge_partial(r0, xrv, attv);
        float l1 = edge_partial(r1, xrv, attv);
#pragma unroll
        for (int o = 16; o; o >>= 1) {
            l0 += __shfl_xor_sync(0xffffffffu, l0, o);
            l1 += __shfl_xor_sync(0xffffffffu, l1, o);
        }
        online_update(l0, r0, m, denom, acc);
        online_update(l1, r1, m, denom, acc);
    }
    if (p < s1) {
        int i0 = g_csr_src[p];
        float4 r0 = xl[i0 * 32 + lane];
        float l0 = edge_partial(r0, xrv, attv);
#pragma unroll
        for (int o = 16; o; o >>= 1) l0 += __shfl_xor_sync(0xffffffffu, l0, o);
        online_update(l0, r0, m, denom, acc);
    }

    float inv = (s1 > s0) ? 1.f / denom : 0.f;
    float4 bv = bias[lane];
    float4 o;
    o.x = acc.x * inv + bv.x;
    o.y = acc.y * inv + bv.y;
    o.z = acc.z * inv + bv.z;
    o.w = acc.w * inv + bv.w;
    if (do_bn) {
        float4 gv = gamma[lane], be = beta[lane], mv = mean[lane], vv = var[lane];
        o.x = fmaxf(gv.x * (o.x - mv.x) * rsqrtf(vv.x + BN_EPS) + be.x, 0.f);
        o.y = fmaxf(gv.y * (o.y - mv.y) * rsqrtf(vv.y + BN_EPS) + be.y, 0.f);
        o.z = fmaxf(gv.z * (o.z - mv.z) * rsqrtf(vv.z + BN_EPS) + be.z, 0.f);
        o.w = fmaxf(gv.w * (o.w - mv.w) * rsqrtf(vv.w + BN_EPS) + be.w, 0.f);
    }
    out[d * 32 + lane] = o;
}

// ---------------- pooling: block per graph (batch is sorted) ----------------
__global__ void k_pool() {
    int g = blockIdx.x;
    int t = threadIdx.x;   // 128
    int s = g_gstart[g], e = g_gstart[g + 1];
    float sum = 0.f;
    for (int r = s; r < e; r++) sum += g_h2[r * 128 + t];
    int cnt = e - s;
    g_pooled[g * 128 + t] = sum / (float)(cnt > 0 ? cnt : 1);
}

// ---------------- fused head: fc1(+bias,relu) tile + fc3 + sigmoid ----------------
__global__ void k_head(const float* __restrict__ fc1w, const float* __restrict__ fc1b,
                       const float* __restrict__ fc3w, const float* __restrict__ fc3b,
                       float* __restrict__ out) {
    __shared__ float As[16][65];
    __shared__ float Bs[16][64];
    __shared__ float red[64][17];
    int t = threadIdx.x;
    int tx = t & 15, ty = t >> 4;
    int g0 = blockIdx.x * 64;
    int s = blockIdx.y;
    int colBase = s * 64;
    float acc[4][4] = {};
    for (int k0 = 0; k0 < 128; k0 += 16) {
#pragma unroll
        for (int i = 0; i < 4; i++) {
            int e = t + i * 256;
            int r = e >> 4, kk = e & 15;
            int gg = g0 + r;
            As[kk][r] = (gg < Gg) ? g_pooled[gg * 128 + k0 + kk] : 0.f;
        }
#pragma unroll
        for (int i = 0; i < 4; i++) {
            int e = t + i * 256;
            int kk = e >> 6, c = e & 63;
            Bs[kk][c] = fc1w[(k0 + kk) * (NSs * M0) + colBase + c];
        }
        __syncthreads();
#pragma unroll
        for (int kk = 0; kk < 16; kk++) {
            float a[4], b[4];
#pragma unroll
            for (int r = 0; r < 4; r++) a[r] = As[kk][ty * 4 + r];
#pragma unroll
            for (int c = 0; c < 4; c++) b[c] = Bs[kk][tx * 4 + c];
#pragma unroll
            for (int r = 0; r < 4; r++)
#pragma unroll
                for (int c = 0; c < 4; c++) acc[r][c] += a[r] * b[c];
        }
        __syncthreads();
    }
#pragma unroll
    for (int r = 0; r < 4; r++) {
        float p = 0.f;
#pragma unroll
        for (int c = 0; c < 4; c++) {
            int j = tx * 4 + c;
            float v = acc[r][c] + fc1b[colBase + j];
            v = fmaxf(v, 0.f);
            p += v * fc3w[j];
        }
        red[ty * 4 + r][tx] = p;
    }
    __syncthreads();
    if (t < 64) {
        float v = 0.f;
#pragma unroll
        for (int i = 0; i < 16; i++) v += red[t][i];
        v += fc3b[0];
        float o = 1.f / (1.f + expf(-v));
        int g = g0 + t;
        if (g < Gg) out[g * NSs + s] = o;
    }
}

// ---------------- launch ----------------
extern "C" void kernel_launch(void* const* d_in, const int* in_sizes, int n_in,
                              void* d_out, int out_size) {
    const float* x     = (const float*)d_in[0];
    const int*   gd    = (const int*)d_in[1];
    const int*   batch = (const int*)d_in[2];
    const float* wl0   = (const float*)d_in[3];
    const float* bl0   = (const float*)d_in[4];
    const float* wr0   = (const float*)d_in[5];
    const float* br0   = (const float*)d_in[6];
    const float* att0  = (const float*)d_in[7];
    const float* b0    = (const float*)d_in[8];
    const float* wl1   = (const float*)d_in[9];
    const float* bl1   = (const float*)d_in[10];
    const float* wr1   = (const float*)d_in[11];
    const float* br1   = (const float*)d_in[12];
    const float* att1  = (const float*)d_in[13];
    const float* b1    = (const float*)d_in[14];
    const float* bn_g  = (const float*)d_in[15];
    const float* bn_b  = (const float*)d_in[16];
    const float* bn_m  = (const float*)d_in[17];
    const float* bn_v  = (const float*)d_in[18];
    const float* fc1w  = (const float*)d_in[19];
    const float* fc1b  = (const float*)d_in[20];
    const float* fc3w  = (const float*)d_in[21];
    const float* fc3b  = (const float*)d_in[22];
    float* out = (float*)d_out;

    // real device addresses (NOT the host shadow symbols)
    float *p_xl, *p_xr, *p_h1, *p_h2;
    cudaGetSymbolAddress((void**)&p_xl, g_xl);
    cudaGetSymbolAddress((void**)&p_xr, g_xr);
    cudaGetSymbolAddress((void**)&p_h1, g_h1);
    cudaGetSymbolAddress((void**)&p_h2, g_h2);

    const int GB = (Nn + 63) / 64;   // 782

    // launch order: index 3 (ncu's capture slot) = fused GEMM layer 0
    k_decode_zero<<<(Ee + 255) / 256, 256>>>(gd);                       // 0
    k_hist<<<(Ee + 255) / 256, 256>>>(batch);                           // 1
    k_scan1<<<SCAN_NB, SCAN_BLK>>>();                                   // 2
    k_gemm_dual<<<GB, 256>>>(x, wl0, bl0, p_xl, wr0, br0, p_xr, Nn);    // 3  <- profiled
    k_scan2p<<<1, 512>>>();                                             // 4
    k_scan3<<<(Nn + 255) / 256, 256>>>();                               // 5
    k_fill<<<(Ee + 255) / 256, 256>>>();                                // 6
    k_aggregate<<<(Nn * 32 + 255) / 256, 256>>>(                        // 7
        (const float4*)p_xl, (const float4*)p_xr,
        (const float4*)att0, (const float4*)b0, (float4*)p_h1,
        1, (const float4*)bn_g, (const float4*)bn_b,
        (const float4*)bn_m, (const float4*)bn_v);
    k_gemm_dual<<<GB, 256>>>(p_h1, wl1, bl1, p_xl, wr1, br1, p_xr, Nn); // 8
    k_aggregate<<<(Nn * 32 + 255) / 256, 256>>>(                        // 9
        (const float4*)p_xl, (const float4*)p_xr,
        (const float4*)att1, (const float4*)b1, (float4*)p_h2,
        0, (const float4*)0, (const float4*)0,
        (const float4*)0, (const float4*)0);
    k_pool<<<Gg, 128>>>();                                              // 10
    dim3 hgrid((Gg + 63) / 64, NSs);
    k_head<<<hgrid, 256>>>(fc1w, fc1b, fc3w, fc3b, out);                // 11
    (void)in_sizes; (void)n_in; (void)out_size;
}